// round 13
// baseline (speedup 1.0000x reference)
#include <cuda_runtime.h>
#include <math.h>

#define NB    8192
#define ND    512
#define NK    8
#define FULL  0xffffffffu

#define THREADS 256
#define WARPS   (THREADS / 32)
#define NBLK    (NB / WARPS)

// ---- prep kernel geometry: block 0 sorts, blocks 1..64 compute norms ----
#define PT        256
#define PGRID     65
#define NBKT      8192
#define PREP_SMEM (NB * 8 + NBKT * 4 * 2 + 32)   // sOut + hist + cur ≈ 131 KB

__device__ double g_acc;
__device__ int    g_done = 0;
__device__ float  g_slab[NB];   // labels in sorted order
__device__ int    g_sidx[NB];   // original row per sorted position
__device__ float  g_norm[NB];   // sum(x^2) per original row

// -------- Prep kernel ----------------------------------------------------
// block 0: exact bucket sort on packed keys (label_bits<<13 | idx).
//   bucket = floor(v*8192) is monotone in v; within-bucket repair by key ->
//   (bucket asc, key asc) == global key order == exact permutation.
// blocks 1..64: per-row sum of squares (also warms S into L2 for main).
__global__ void __launch_bounds__(PT) nest_prep_kernel(
    const float* __restrict__ L, const float* __restrict__ S)
{
    const int tid  = threadIdx.x;
    const int lane = tid & 31;
    const int wid  = tid >> 5;

    if (blockIdx.x != 0) {
        // ---------------- norm blocks ----------------
        const int rbase = (blockIdx.x - 1) * 128;
        const float4* Sf4 = (const float4*)S;
#pragma unroll 1
        for (int j = 0; j < 16; j++) {
            const int row = rbase + wid + j * 8;
            float s = 0.0f;
#pragma unroll
            for (int t = 0; t < 4; t++) {
                float4 x = Sf4[(size_t)row * 128 + lane + t * 32];
                s += x.x * x.x + x.y * x.y + x.z * x.z + x.w * x.w;
            }
#pragma unroll
            for (int off = 16; off > 0; off >>= 1)
                s += __shfl_xor_sync(FULL, s, off);
            if (lane == 0) g_norm[row] = s;
        }
        return;
    }

    // ---------------- sort block ----------------
    extern __shared__ char sm[];
    unsigned long long* sOut  = (unsigned long long*)sm;   // [NB]
    int*                sHist = (int*)(sOut + NB);         // [NBKT]
    int*                sCur  = sHist + NBKT;              // [NBKT]
    int*                sWarp = sCur + NBKT;               // [8]

    if (tid == 0) g_acc = 0.0;

    for (int i = tid; i < NBKT; i += PT) sHist[i] = 0;
    __syncthreads();

    // pass 1: histogram
    for (int i = tid; i < NB; i += PT) {
        int b = (int)(L[i] * (float)NBKT);
        b = max(0, min(b, NBKT - 1));
        atomicAdd(&sHist[b], 1);
    }
    __syncthreads();

    // exclusive prefix sum: 32 buckets/thread, warp + block scan
    const int base = tid * 32;
    int sum = 0;
    for (int j = 0; j < 32; j++) sum += sHist[base + j];

    int v = sum;
#pragma unroll
    for (int off = 1; off < 32; off <<= 1) {
        int o = __shfl_up_sync(FULL, v, off);
        if (lane >= off) v += o;
    }
    if (lane == 31) sWarp[wid] = v;
    __syncthreads();
    if (wid == 0 && lane < 8) {
        int wv = sWarp[lane];
#pragma unroll
        for (int off = 1; off < 8; off <<= 1) {
            int o = __shfl_up_sync(0xFFu, wv, off);
            if (lane >= off) wv += o;
        }
        sWarp[lane] = wv;
    }
    __syncthreads();
    int running = ((wid > 0) ? sWarp[wid - 1] : 0) + v - sum;
    for (int j = 0; j < 32; j++) {
        int c = sHist[base + j];
        sHist[base + j] = running;
        sCur[base + j]  = running;
        running += c;
    }
    __syncthreads();

    // pass 2: scatter packed keys (L is L1-hot from pass 1)
    for (int i = tid; i < NB; i += PT) {
        float val = L[i];
        int b = max(0, min((int)(val * (float)NBKT), NBKT - 1));
        int pos = atomicAdd(&sCur[b], 1);
        sOut[pos] = ((unsigned long long)__float_as_uint(val) << 13) | (unsigned)i;
    }
    __syncthreads();

    // repair: insertion sort inside each bucket (load factor 1, mostly <=1)
    for (int b = tid; b < NBKT; b += PT) {
        int st = sHist[b];
        int en = sCur[b];
        for (int i = st + 1; i < en; i++) {
            unsigned long long key = sOut[i];
            int j = i - 1;
            while (j >= st && sOut[j] > key) { sOut[j + 1] = sOut[j]; j--; }
            sOut[j + 1] = key;
        }
    }
    __syncthreads();

    // emit sorted label / original index
    for (int r = tid; r < NB; r += PT) {
        unsigned long long k = sOut[r];
        g_slab[r] = __uint_as_float((unsigned)(k >> 13));
        g_sidx[r] = (int)(k & 0x1FFFu);
    }
}

// ------------- Main kernel: warp per sorted row, lane-parallel select -------
__global__ void __launch_bounds__(THREADS) nest_main_kernel(
    const float* __restrict__ S, float* __restrict__ out)
{
    __shared__ double sSim[WARPS];

    const int tid  = threadIdx.x;
    const int wid  = tid >> 5;
    const int lane = tid & 31;

    const int r = blockIdx.x * WARPS + wid;     // sorted position

    // --- lane-parallel window select: lanes 0..14 hold candidates r-7..r+7 ---
    const int  p     = r - 7 + lane;
    const bool valid = (lane < 15) && (p >= 0) && (p < NB);
    float lab = valid ? g_slab[p] : 0.0f;
    int   gi  = valid ? g_sidx[p] : 0;

    const float Lb = __shfl_sync(FULL, lab, 7); // lane 7 == self (p == r)
    float d = valid ? fabsf(lab - Lb) : INFINITY;

    int rank = 0;
#pragma unroll
    for (int src = 0; src < 15; src++) {
        float od = __shfl_sync(FULL, d, src);
        rank += (od < d) | ((od == d) & (src < lane));   // unique ranks
    }
    const bool sel = (rank < NK) && valid;

    float e = sel ? __expf(-d * d * (1.0f / 50.0f)) : 0.0f;  // 2*STD^2 = 50
    float wsum = e;
#pragma unroll
    for (int off = 16; off > 0; off >>= 1)
        wsum += __shfl_xor_sync(FULL, wsum, off);
    const float winv = 1.0f / wsum;

    int   gidx[NK];
    float w[NK];
#pragma unroll
    for (int k = 0; k < NK; k++) {
        unsigned m  = __ballot_sync(FULL, sel && (rank == k));
        int      sl = __ffs(m) - 1;
        gidx[k] = __shfl_sync(FULL, gi, sl);
        w[k]    = __shfl_sync(FULL, e,  sl) * winv;
    }
    const int b = __shfl_sync(FULL, gi, 7);     // original self row

    // --- fused gather + weighted mean + cosine terms (nx precomputed) ---
    const float4* xr = (const float4*)(S + (size_t)b * ND);
    float4 x[4];
#pragma unroll
    for (int t = 0; t < 4; t++) x[t] = xr[lane + t * 32];

    float dot = 0.0f, nm = 0.0f;

#pragma unroll
    for (int t = 0; t < 4; t++) {
        int col = lane + t * 32;
        float mx = 0.0f, my = 0.0f, mz = 0.0f, mw = 0.0f;
#pragma unroll
        for (int k = 0; k < NK; k++) {
            float4 s = ((const float4*)(S + (size_t)gidx[k] * ND))[col];
            mx = fmaf(w[k], s.x, mx);
            my = fmaf(w[k], s.y, my);
            mz = fmaf(w[k], s.z, mz);
            mw = fmaf(w[k], s.w, mw);
        }
        dot += x[t].x * mx + x[t].y * my + x[t].z * mz + x[t].w * mw;
        nm  += mx * mx + my * my + mz * mz + mw * mw;
    }

#pragma unroll
    for (int off = 16; off > 0; off >>= 1) {
        dot += __shfl_xor_sync(FULL, dot, off);
        nm  += __shfl_xor_sync(FULL, nm,  off);
    }

    if (lane == 0) {
        float nx  = g_norm[b];
        float sim = dot / ((1e-10f + sqrtf(nx)) * (1e-10f + sqrtf(nm)));
        sSim[wid] = (double)sim;
    }
    __syncthreads();

    if (tid == 0) {
        double bs = 0.0;
#pragma unroll
        for (int k = 0; k < WARPS; k++) bs += sSim[k];
        atomicAdd(&g_acc, bs);
        __threadfence();
        int old = atomicAdd(&g_done, 1);
        if (old == NBLK - 1) {                  // last block finalizes
            double total = *((volatile double*)&g_acc);
            out[0] = (float)(1.0 - total / (double)NB);
            g_done = 0;                         // reset for graph replay
        }
    }
}

extern "C" void kernel_launch(void* const* d_in, const int* in_sizes, int n_in,
                              void* d_out, int out_size)
{
    const float* S = (const float*)d_in[0];   // Struct [8192, 512]
    const float* L = (const float*)d_in[1];   // Label  [8192]
    float* out = (float*)d_out;

    (void)cudaFuncSetAttribute(nest_prep_kernel,
                               cudaFuncAttributeMaxDynamicSharedMemorySize,
                               PREP_SMEM);

    nest_prep_kernel<<<PGRID, PT, PREP_SMEM>>>(L, S);
    nest_main_kernel<<<NBLK, THREADS>>>(S, out);
}

// round 14
// speedup vs baseline: 2.0783x; 2.0783x over previous
#include <cuda_runtime.h>
#include <math.h>

#define NB    8192
#define ND    512
#define NK    8
#define FULL  0xffffffffu

#define THREADS 256
#define WARPS   (THREADS / 32)
#define NBLK    (NB / WARPS)

// ---- prep kernel geometry: block 0 sorts (R12 config), 1..128 do norms ----
#define ST    1024
#define PGRID 129
#define NBKT  8192
#define SORT_SMEM (NB * 8 * 2 + NBKT * 4 * 2 + 64 * 4)   // 196864 B

__device__ double g_acc;
__device__ int    g_done = 0;
__device__ float  g_slab[NB];   // labels in sorted order
__device__ int    g_sidx[NB];   // original row per sorted position
__device__ float  g_norm[NB];   // sum(x^2) per original row

// -------- Prep kernel: block 0 = R12 bucket sort; blocks 1..128 = norms ----
// key = label_bits<<13 | idx  (labels nonneg -> uint order == float order;
// idx makes keys unique). bucket = floor(v*8192) is monotone in v, so
// (bucket asc, key asc within bucket) == global key order. Repair pass
// insertion-sorts the (rare) multi-element buckets -> exact permutation.
__global__ void __launch_bounds__(ST) nest_prep_kernel(
    const float* __restrict__ L, const float* __restrict__ S)
{
    const int tid  = threadIdx.x;
    const int lane = tid & 31;
    const int wid  = tid >> 5;

    if (blockIdx.x != 0) {
        // ---------------- norm blocks: 64 rows each, 2 rows/warp ------------
        const int rbase = (blockIdx.x - 1) * 64;
        const float4* Sf4 = (const float4*)S;
#pragma unroll
        for (int j = 0; j < 2; j++) {
            const int row = rbase + wid * 2 + j;
            float s = 0.0f;
#pragma unroll
            for (int t = 0; t < 4; t++) {
                float4 x = Sf4[(size_t)row * 128 + lane + t * 32];
                s += x.x * x.x + x.y * x.y + x.z * x.z + x.w * x.w;
            }
#pragma unroll
            for (int off = 16; off > 0; off >>= 1)
                s += __shfl_xor_sync(FULL, s, off);
            if (lane == 0) g_norm[row] = s;
        }
        return;
    }

    // ---------------- sort block (R12 verbatim) ----------------
    extern __shared__ char sm[];
    unsigned long long* sKey  = (unsigned long long*)sm;          // [NB]
    unsigned long long* sOut  = sKey + NB;                        // [NB]
    int*                sHist = (int*)(sOut + NB);                // [NBKT]
    int*                sCur  = sHist + NBKT;                     // [NBKT]
    int*                sWarp = sCur + NBKT;                      // [64]

    if (tid == 0) g_acc = 0.0;

    for (int i = tid; i < NBKT; i += ST) sHist[i] = 0;
    __syncthreads();

    // load labels, build keys, histogram
    for (int i = tid; i < NB; i += ST) {
        float v = L[i];
        sKey[i] = ((unsigned long long)__float_as_uint(v) << 13) | (unsigned)i;
        int b = (int)(v * (float)NBKT);
        b = max(0, min(b, NBKT - 1));
        atomicAdd(&sHist[b], 1);
    }
    __syncthreads();

    // exclusive prefix sum over NBKT counters (8 per thread + block scan)
    const int base = tid * 8;
    int local[8];
    int sum = 0;
#pragma unroll
    for (int j = 0; j < 8; j++) { local[j] = sum; sum += sHist[base + j]; }

    int v = sum;                                   // inclusive scan of sums
#pragma unroll
    for (int off = 1; off < 32; off <<= 1) {
        int o = __shfl_up_sync(FULL, v, off);
        if (lane >= off) v += o;
    }
    if (lane == 31) sWarp[wid] = v;                // warp totals
    __syncthreads();
    if (wid == 0) {
        int wv = sWarp[lane];                      // 32 warps
#pragma unroll
        for (int off = 1; off < 32; off <<= 1) {
            int o = __shfl_up_sync(FULL, wv, off);
            if (lane >= off) wv += o;
        }
        sWarp[lane] = wv;                          // inclusive across warps
    }
    __syncthreads();
    const int warpBase = (wid > 0) ? sWarp[wid - 1] : 0;
    const int myExcl   = warpBase + v - sum;
#pragma unroll
    for (int j = 0; j < 8; j++) {
        int s = myExcl + local[j];
        sHist[base + j] = s;                       // bucket start (preserved)
        sCur[base + j]  = s;                       // cursor
    }
    __syncthreads();

    // scatter into bucket slots (arbitrary order within bucket)
    for (int i = tid; i < NB; i += ST) {
        unsigned long long k = sKey[i];
        float val = __uint_as_float((unsigned)(k >> 13));
        int b = max(0, min((int)(val * (float)NBKT), NBKT - 1));
        int pos = atomicAdd(&sCur[b], 1);
        sOut[pos] = k;
    }
    __syncthreads();

    // repair: insertion sort inside each bucket segment (tiny, mostly <=1)
    for (int b = tid; b < NBKT; b += ST) {
        int st = sHist[b];
        int en = sCur[b];
        for (int i = st + 1; i < en; i++) {
            unsigned long long key = sOut[i];
            int j = i - 1;
            while (j >= st && sOut[j] > key) { sOut[j + 1] = sOut[j]; j--; }
            sOut[j + 1] = key;
        }
    }
    __syncthreads();

    // emit sorted label / original index
    for (int r = tid; r < NB; r += ST) {
        unsigned long long k = sOut[r];
        g_slab[r] = __uint_as_float((unsigned)(k >> 13));
        g_sidx[r] = (int)(k & 0x1FFFu);
    }
}

// ------------- Main kernel (R12 two-pointer select) -------------------------
__global__ void __launch_bounds__(THREADS) nest_main_kernel(
    const float* __restrict__ S, float* __restrict__ out)
{
    __shared__ double sSim[WARPS];

    const int tid  = threadIdx.x;
    const int wid  = tid >> 5;
    const int lane = tid & 31;

    const int r  = blockIdx.x * WARPS + wid;    // sorted position
    const float Lb = g_slab[r];
    const int   b  = g_sidx[r];                 // original row

    // hoist self-row loads: independent of the select chain below -> MLP
    const float4* xr = (const float4*)(S + (size_t)b * ND);
    float4 x[4];
#pragma unroll
    for (int t = 0; t < 4; t++) x[t] = xr[lane + t * 32];

    // two-pointer nearest-8 over the sorted window (broadcast loads)
    int   gidx[NK];
    float w[NK];
    gidx[0] = b; w[0] = 1.0f;
    float wsum = 1.0f;

    int lo = r - 1, hi = r + 1;
#pragma unroll
    for (int k = 1; k < NK; k++) {
        float dl = (lo >= 0) ? Lb - g_slab[lo] : INFINITY;
        float dh = (hi < NB) ? g_slab[hi] - Lb : INFINITY;
        float d; int gi;
        if (dl <= dh) { gi = g_sidx[lo]; d = dl; lo--; }
        else          { gi = g_sidx[hi]; d = dh; hi++; }
        gidx[k] = gi;
        float e = __expf(-d * d * (1.0f / 50.0f));   // 2*STD^2 = 50
        w[k] = e; wsum += e;
    }

    const float winv = 1.0f / wsum;
#pragma unroll
    for (int k = 0; k < NK; k++) w[k] *= winv;

    // fused gather + weighted mean + cosine terms (nx precomputed in prep)
    float dot = 0.0f, nm = 0.0f;

#pragma unroll
    for (int t = 0; t < 4; t++) {
        int col = lane + t * 32;
        float mx = 0.0f, my = 0.0f, mz = 0.0f, mw = 0.0f;
#pragma unroll
        for (int k = 0; k < NK; k++) {
            float4 s = ((const float4*)(S + (size_t)gidx[k] * ND))[col];
            mx = fmaf(w[k], s.x, mx);
            my = fmaf(w[k], s.y, my);
            mz = fmaf(w[k], s.z, mz);
            mw = fmaf(w[k], s.w, mw);
        }
        dot += x[t].x * mx + x[t].y * my + x[t].z * mz + x[t].w * mw;
        nm  += mx * mx + my * my + mz * mz + mw * mw;
    }

#pragma unroll
    for (int off = 16; off > 0; off >>= 1) {
        dot += __shfl_xor_sync(FULL, dot, off);
        nm  += __shfl_xor_sync(FULL, nm,  off);
    }

    if (lane == 0) {
        float nx  = g_norm[b];
        float sim = dot / ((1e-10f + sqrtf(nx)) * (1e-10f + sqrtf(nm)));
        sSim[wid] = (double)sim;
    }
    __syncthreads();

    if (tid == 0) {
        double bs = 0.0;
#pragma unroll
        for (int k = 0; k < WARPS; k++) bs += sSim[k];
        atomicAdd(&g_acc, bs);
        __threadfence();
        int old = atomicAdd(&g_done, 1);
        if (old == NBLK - 1) {                  // last block finalizes
            double total = *((volatile double*)&g_acc);
            out[0] = (float)(1.0 - total / (double)NB);
            g_done = 0;                         // reset for graph replay
        }
    }
}

extern "C" void kernel_launch(void* const* d_in, const int* in_sizes, int n_in,
                              void* d_out, int out_size)
{
    const float* S = (const float*)d_in[0];   // Struct [8192, 512]
    const float* L = (const float*)d_in[1];   // Label  [8192]
    float* out = (float*)d_out;

    (void)cudaFuncSetAttribute(nest_prep_kernel,
                               cudaFuncAttributeMaxDynamicSharedMemorySize,
                               SORT_SMEM);

    nest_prep_kernel<<<PGRID, ST, SORT_SMEM>>>(L, S);
    nest_main_kernel<<<NBLK, THREADS>>>(S, out);
}